// round 15
// baseline (speedup 1.0000x reference)
#include <cuda_runtime.h>
#include <cooperative_groups.h>

namespace cg = cooperative_groups;

// Problem shape (fixed by reference setup_inputs): [B=64, S=2048, D=512] fp32
constexpr int B = 64;
constexpr int S = 2048;
constexpr int D = 512;
constexpr int D4 = D / 4;                      // 128 float4 per row
constexpr int CHUNK = 16;                      // timesteps per warp
constexpr int THREADS = 256;                   // 8 warps/block (measured best shape)
constexpr int WARPS_PER_BLOCK = THREADS / 32;  // 8
constexpr int ROWS_PER_BLOCK = WARPS_PER_BLOCK * CHUNK;       // 128
constexpr int BLOCKS_PER_BATCH = S / ROWS_PER_BLOCK;          // 16 = cluster size
constexpr int GRID1 = B * BLOCKS_PER_BATCH;                   // 1024 blocks

__device__ __forceinline__ float4 ldcs4(const float4* p) {
    return __ldcs(p);   // streaming: read-once data, don't fight for L2 residency
}

// Single kernel: R13 streaming body + HW cluster barrier for the per-batch max.
// One cluster (16 CTAs) = one batch. No atomics, no software spin.
// R14 bug fixed: a trailing cluster.sync() prevents any CTA from exiting while
// a sibling may still be reading its s_bmax via DSMEM (the missing exit barrier
// caused R14's 'unspecified launch failure').
__global__ void __launch_bounds__(THREADS)
__cluster_dims__(BLOCKS_PER_BATCH, 1, 1)
l2_fused_cluster_kernel(const float4* __restrict__ x, float* __restrict__ out) {
    __shared__ float4 s_bound[WARPS_PER_BLOCK * 128];  // 8 rows x 512 floats = 16KB
    __shared__ float  s_wmax[WARPS_PER_BLOCK];
    __shared__ float  s_bmax;                          // this block's max (DSMEM-visible)

    cg::cluster_group cluster = cg::this_cluster();

    const int b    = blockIdx.x / BLOCKS_PER_BATCH;
    const int r0   = (blockIdx.x % BLOCKS_PER_BATCH) * ROWS_PER_BLOCK;
    const int w    = threadIdx.x >> 5;
    const int lane = threadIdx.x & 31;
    const int s0   = r0 + w * CHUNK;

    const float4* base = x + (size_t)b * S * D4;
    float* orow = out + (size_t)b * S;

    // Phase 1: load my chunk's LAST row; share it with warp w+1 via smem.
    float4 last[4];
    {
        const float4* rl = base + (size_t)(s0 + CHUNK - 1) * D4 + lane;
        #pragma unroll
        for (int j = 0; j < 4; ++j) last[j] = ldcs4(rl + 32 * j);
        float4* sm = s_bound + w * 128 + lane;
        #pragma unroll
        for (int j = 0; j < 4; ++j) sm[32 * j] = last[j];
    }

    // Warp 0 also loads the block's global boundary row.
    float4 prev[4];
    const bool first_chunk = (r0 == 0) && (w == 0);
    if (w == 0) {
        const int sprev = (r0 == 0) ? 0 : (r0 - 1);
        const float4* rp = base + (size_t)sprev * D4 + lane;
        #pragma unroll
        for (int j = 0; j < 4; ++j) prev[j] = ldcs4(rp + 32 * j);
    }

    __syncthreads();

    if (w != 0) {
        const float4* sp = s_bound + (w - 1) * 128 + lane;
        #pragma unroll
        for (int j = 0; j < 4; ++j) prev[j] = sp[32 * j];
    }

    const int s_start = first_chunk ? 1 : s0;   // first chunk: d[0] = 0 (banked)
    const int s_last  = s0 + CHUNK - 1;

    float wmax  = 0.0f;  // d >= 0 everywhere (and d[0] = 0)
    float mysum = 0.0f;  // lane (s - s0) banks row s's sum; lane 0 of the first
                         // chunk never matches (s starts at s0+1) -> keeps 0 = d[0]

    for (int s = s_start; s <= s_last; ++s) {
        float4 cur[4];
        if (s < s_last) {
            const float4* row = base + (size_t)s * D4 + lane;
            #pragma unroll
            for (int j = 0; j < 4; ++j) cur[j] = ldcs4(row + 32 * j);
        } else {
            #pragma unroll
            for (int j = 0; j < 4; ++j) cur[j] = last[j];
        }

        float sum = 0.0f;
        #pragma unroll
        for (int j = 0; j < 4; ++j) {
            float dx = cur[j].x - prev[j].x;
            float dy = cur[j].y - prev[j].y;
            float dz = cur[j].z - prev[j].z;
            float dw = cur[j].w - prev[j].w;
            sum += dx * dx + dy * dy + dz * dz + dw * dw;
        }
        // warp reduce (sum over D); all lanes end with the full sum
        #pragma unroll
        for (int off = 16; off > 0; off >>= 1)
            sum += __shfl_xor_sync(0xffffffffu, sum, off);
        wmax = fmaxf(wmax, sum);
        if (s - s0 == lane) mysum = sum;        // bank in register

        #pragma unroll
        for (int j = 0; j < 4; ++j) prev[j] = cur[j];
    }

    // Block max -> this block's smem slot.
    if (lane == 0) s_wmax[w] = wmax;
    __syncthreads();
    if (threadIdx.x == 0) {
        float m = s_wmax[0];
        #pragma unroll
        for (int i = 1; i < WARPS_PER_BLOCK; ++i) m = fmaxf(m, s_wmax[i]);
        s_bmax = m;
    }

    // HW cluster barrier: all 16 sibling CTAs' maxes are published.
    cluster.sync();

    // Every warp reads the 16 sibling maxes via DSMEM (lanes 0..15, parallel).
    float m;
    {
        const float* remote = cluster.map_shared_rank(&s_bmax, lane & 15);
        m = *remote;
    }
    #pragma unroll
    for (int off = 8; off > 0; off >>= 1)
        m = fmaxf(m, __shfl_xor_sync(0xffffffffu, m, off));
    const float inv = 1.0f / m;

    // Single normalized write: one coalesced 64B store per warp.
    if (lane < CHUNK) orow[s0 + lane] = mysum * inv;

    // Exit barrier: no CTA may retire while a sibling could still be reading
    // its s_bmax via DSMEM (this was R14's failure).
    cluster.sync();
}

extern "C" void kernel_launch(void* const* d_in, const int* in_sizes, int n_in,
                              void* d_out, int out_size) {
    const float4* x = (const float4*)d_in[0];
    (void)in_sizes; (void)n_in; (void)out_size;

    // Cluster size 16 > 8 requires the non-portable opt-in (idempotent; host-side
    // attribute set, not a stream/graph op).
    cudaFuncSetAttribute(l2_fused_cluster_kernel,
                         cudaFuncAttributeNonPortableClusterSizeAllowed, 1);

    l2_fused_cluster_kernel<<<GRID1, THREADS>>>(x, (float*)d_out);
}

// round 17
// speedup vs baseline: 1.0375x; 1.0375x over previous
#include <cuda_runtime.h>
#include <cstdint>

// Problem shape (fixed by reference setup_inputs): [B=64, S=2048, D=512] fp32
constexpr int B = 64;
constexpr int S = 2048;
constexpr int D = 512;
constexpr int D4 = D / 4;                      // 128 float4 per row
constexpr int CHUNK = 32;                      // timesteps per warp (= lane count)
constexpr int THREADS = 256;                   // 8 warps/block
constexpr int WARPS_PER_BLOCK = THREADS / 32;  // 8
constexpr int ROWS_PER_BLOCK = WARPS_PER_BLOCK * CHUNK;       // 256
constexpr int CLUSTER = S / ROWS_PER_BLOCK;                   // 8 (portable size)
constexpr int GRID1 = B * CLUSTER;                            // 512 blocks, 1 wave

__device__ __forceinline__ float4 ldcs4(const float4* p) {
    return __ldcs(p);   // streaming: read-once data
}

__device__ __forceinline__ uint32_t smem_u32(const void* p) {
    return (uint32_t)__cvta_generic_to_shared(p);
}

// Single fused kernel, register-lean cluster version.
// R15 lesson: CG machinery + boundary-sharing pushed regs to 60 -> 4 CTAs/SM ->
// 5.1 TB/s. This version: no smem boundary sharing (prev[4] only), raw PTX
// cluster barriers + mapa, cluster size 8 (portable). Sums banked in registers
// (all 32 lanes), single normalized 128B store per warp at the end.
__global__ void __launch_bounds__(THREADS)
__cluster_dims__(CLUSTER, 1, 1)
l2_fused_cluster_kernel(const float4* __restrict__ x, float* __restrict__ out) {
    __shared__ float s_wmax[WARPS_PER_BLOCK];
    __shared__ float s_bmax;                   // this block's max (DSMEM-visible)

    const int b    = blockIdx.x / CLUSTER;
    const int rank = blockIdx.x % CLUSTER;     // == cluster cta rank (x-major)
    const int r0   = rank * ROWS_PER_BLOCK;
    const int w    = threadIdx.x >> 5;
    const int lane = threadIdx.x & 31;
    const int s0   = r0 + w * CHUNK;

    const float4* base = x + (size_t)b * S * D4;
    float* orow = out + (size_t)b * S;

    // previous row: s0-1, except the very first chunk where d[0] = 0
    const int sprev = (s0 == 0) ? 0 : (s0 - 1);
    const float4* rp = base + (size_t)sprev * D4 + lane;
    float4 prev[4];
    #pragma unroll
    for (int j = 0; j < 4; ++j) prev[j] = ldcs4(rp + 32 * j);

    const int s_start = (s0 == 0) ? 1 : s0;    // first chunk: lane 0 keeps d[0]=0
    const int s_end   = s0 + CHUNK;

    float wmax  = 0.0f;   // d >= 0 everywhere (and d[0] = 0)
    float mysum = 0.0f;   // lane (s - s0) banks row s's sum

    for (int s = s_start; s < s_end; ++s) {
        const float4* row = base + (size_t)s * D4 + lane;
        float sum = 0.0f;
        #pragma unroll
        for (int j = 0; j < 4; ++j) {
            float4 c = ldcs4(row + 32 * j);
            float dx = c.x - prev[j].x;
            float dy = c.y - prev[j].y;
            float dz = c.z - prev[j].z;
            float dw = c.w - prev[j].w;
            sum += dx * dx + dy * dy + dz * dz + dw * dw;
            prev[j] = c;
        }
        // warp reduce (sum over D); all lanes end with the full sum
        #pragma unroll
        for (int off = 16; off > 0; off >>= 1)
            sum += __shfl_xor_sync(0xffffffffu, sum, off);
        wmax = fmaxf(wmax, sum);
        if (s - s0 == lane) mysum = sum;        // bank in register
    }

    // Block max -> this block's smem slot.
    if (lane == 0) s_wmax[w] = wmax;
    __syncthreads();
    if (threadIdx.x == 0) {
        float m = s_wmax[0];
        #pragma unroll
        for (int i = 1; i < WARPS_PER_BLOCK; ++i) m = fmaxf(m, s_wmax[i]);
        s_bmax = m;
    }

    // Cluster barrier: all 8 sibling CTAs' maxes published.
    asm volatile("barrier.cluster.arrive.aligned;" ::: "memory");
    asm volatile("barrier.cluster.wait.aligned;" ::: "memory");

    // Each lane reads one of the 8 sibling maxes via DSMEM (mapa), shuffle-max.
    float m;
    {
        uint32_t local = smem_u32(&s_bmax);
        uint32_t remote;
        asm volatile("mapa.shared::cluster.u32 %0, %1, %2;"
                     : "=r"(remote) : "r"(local), "r"(lane & 7));
        asm volatile("ld.shared::cluster.f32 %0, [%1];"
                     : "=f"(m) : "r"(remote));
    }
    #pragma unroll
    for (int off = 4; off > 0; off >>= 1)
        m = fmaxf(m, __shfl_xor_sync(0xffffffffu, m, off));
    const float inv = 1.0f / m;

    // Single normalized write: one coalesced 128B store per warp.
    orow[s0 + lane] = mysum * inv;

    // Exit barrier: no CTA may retire while a sibling could still be reading
    // its s_bmax via DSMEM (R14's failure mode).
    asm volatile("barrier.cluster.arrive.aligned;" ::: "memory");
    asm volatile("barrier.cluster.wait.aligned;" ::: "memory");
}

extern "C" void kernel_launch(void* const* d_in, const int* in_sizes, int n_in,
                              void* d_out, int out_size) {
    const float4* x = (const float4*)d_in[0];
    (void)in_sizes; (void)n_in; (void)out_size;

    l2_fused_cluster_kernel<<<GRID1, THREADS>>>(x, (float*)d_out);
}